// round 1
// baseline (speedup 1.0000x reference)
#include <cuda_runtime.h>
#include <math.h>
#include <stdint.h>

// Problem constants (fixed shapes from setup_inputs)
#define B      1024
#define L      128
#define KPOS   8
#define NNEG   2048
#define NW     (B*KPOS + NNEG)   // 10240 W rows
#define EDIM   256
#define H      4
#define HD     64
#define P      16
#define M      32
#define R      2
#define NUML   131072
#define ETAB_ROWS 100000

// Quadrature constants computed in double, folded at compile time
#define SQRT2_D 1.4142135623730951
#define CC      2.000001
__device__ __constant__ float c_s[2]   = { (float)((2.0 - SQRT2_D)/CC), (float)((2.0 + SQRT2_D)/CC) };
__device__ __constant__ float c_w[2]   = { (float)((2.0 + SQRT2_D)/(4.0*CC)), (float)((2.0 - SQRT2_D)/(4.0*CC)) };
// 1/sqrt(32.000001)
#define INV_SQRT_M 0.17677669253f

// Scratch (static device globals: allocation-free)
__device__ float d_anch [P*HD];          // normalized anchors
__device__ float d_polyQ[B*H*P];         // [b][h][p]
__device__ float d_prfQ [B*R*H*M];       // [b][r][h][m]
__device__ float d_polyW[NW*H*P];        // [i][h][p]
__device__ float d_prfW [(size_t)NW*R*H*M]; // [i][r][h][m]
__device__ float d_T    [R*H*P*M];       // [r][h][p][m]
__device__ float d_pos  [B*KPOS];
__device__ float d_numer[B];

// ---------------------------------------------------------------- anchors
__global__ void anch_kernel(const float* __restrict__ anchors) {
    __shared__ float red[64];
    int p = blockIdx.x, d = threadIdx.x;
    float v = anchors[p*HD + d];
    red[d] = v*v;
    __syncthreads();
    for (int s = 32; s > 0; s >>= 1) { if (d < s) red[d] += red[d+s]; __syncthreads(); }
    float n = sqrtf(red[0]);                 // reference divides with no eps
    d_anch[p*HD + d] = v / n;
}

// ---------------------------------------------------------------- shared feature math
// sq: shared xr (256, per-head normalized). Writes poly (64) and prf (256) features.
__device__ __forceinline__ void compute_feats(const float* sq,
                                              const float* __restrict__ omega,
                                              float* __restrict__ polyOut,
                                              float* __restrict__ prfOut,
                                              int t) {
    // prf features: thread t -> (r,h,m)
    int r = t >> 7, h = (t >> 5) & 3, m = t & 31;
    const float* x  = sq + h*HD;
    const float* om = omega + (size_t)((r*H + h)*HD)*M + m;
    float acc = 0.f;
    #pragma unroll
    for (int d = 0; d < HD; ++d) acc += x[d] * om[(size_t)d*M];
    acc *= 0.125f;                           // omega / sqrt(HD)
    float s  = c_s[r];
    float arg = acc * sqrtf(2.0f*s) - s;
    arg = fminf(fmaxf(arg, -20.f), 20.f);
    prfOut[t] = expf(arg) * (sqrtf(c_w[r]) * INV_SQRT_M);

    // poly features: threads 0..63 -> (h,p)
    if (t < 64) {
        int hh = t >> 4, p = t & 15;
        const float* xx = sq + hh*HD;
        const float* an = d_anch + p*HD;
        float a = 0.f;
        #pragma unroll
        for (int d = 0; d < HD; ++d) a += xx[d]*an[d];
        a = fminf(fmaxf(a, -1.f), 1.f);
        polyOut[t] = a*a*0.25f;              // ^2 / sqrt(P)
    }
}

// Normalize (full 256 with eps, then per-head with eps), leaves xr in sq.
__device__ __forceinline__ void normalize_row(float v, float* sq, float* red, int t) {
    red[t] = v*v;
    __syncthreads();
    for (int s = 128; s > 0; s >>= 1) { if (t < s) red[t] += red[t+s]; __syncthreads(); }
    float qn = v / fmaxf(sqrtf(red[0]), 1e-4f);
    __syncthreads();
    red[t] = qn*qn;
    __syncthreads();
    for (int s = 32; s > 0; s >>= 1) { if ((t & 63) < s) red[t] += red[t+s]; __syncthreads(); }
    float hn = red[(t >> 6) << 6];
    __syncthreads();
    sq[t] = qn / fmaxf(sqrtf(hn), 1e-4f);
    __syncthreads();
}

// ---------------------------------------------------------------- query features
__global__ void query_feat_kernel(const int* __restrict__ indices,
                                  const float* __restrict__ mask,
                                  const float* __restrict__ embed,
                                  const float* __restrict__ omega) {
    __shared__ float sq[256];
    __shared__ float red[256];
    __shared__ int   sidx[L];
    __shared__ float smk[L];
    int b = blockIdx.x, t = threadIdx.x;

    if (t < L) { sidx[t] = indices[b*L + t]; smk[t] = mask[b*L + t]; }
    __syncthreads();

    float acc = 0.f;
    #pragma unroll 4
    for (int l = 0; l < L; ++l)
        acc += __ldg(embed + (size_t)sidx[l]*EDIM + t) * smk[l];

    // mask sum
    red[t] = (t < L) ? smk[t] : 0.f;
    __syncthreads();
    for (int s = 128; s > 0; s >>= 1) { if (t < s) red[t] += red[t+s]; __syncthreads(); }
    float msum = red[0];
    __syncthreads();

    float q = acc / fmaxf(msum, 1.0f);
    normalize_row(q, sq, red, t);
    compute_feats(sq, omega, d_polyQ + b*H*P, d_prfQ + b*R*H*M, t);
}

// ---------------------------------------------------------------- W features
__global__ void w_feat_kernel(const int* __restrict__ labels,
                              const int* __restrict__ negidx,
                              const float* __restrict__ kernelM,
                              const float* __restrict__ omega) {
    __shared__ float sq[256];
    __shared__ float red[256];
    int i = blockIdx.x, t = threadIdx.x;
    int j = (i < B*KPOS) ? max(labels[i], 0) : negidx[i - B*KPOS];
    float w = __ldg(kernelM + (size_t)t * NUML + j);
    normalize_row(w, sq, red, t);
    compute_feats(sq, omega, d_polyW + i*H*P, d_prfW + (size_t)i*R*H*M, t);
}

// ---------------------------------------------------------------- T = sum over neg rows of polyW x prfW
__global__ void t_kernel() {
    int r = blockIdx.x >> 2, h = blockIdx.x & 3;
    int t = threadIdx.x;                 // 512 threads
    int p = t >> 5, m = t & 31;
    __shared__ float spw[32][16];
    __shared__ float spf[32][32];
    float acc = 0.f;
    for (int base = B*KPOS; base < NW; base += 32) {
        int lr = t >> 4, lp = t & 15;
        spw[lr][lp] = d_polyW[(base + lr)*H*P + h*P + lp];
        int fr = t >> 5, fm = t & 31;
        spf[fr     ][fm] = d_prfW[(size_t)(base+fr   )*R*H*M + r*H*M + h*M + fm];
        spf[fr + 16][fm] = d_prfW[(size_t)(base+fr+16)*R*H*M + r*H*M + h*M + fm];
        __syncthreads();
        #pragma unroll
        for (int k = 0; k < 32; ++k) acc += spw[k][p]*spf[k][m];
        __syncthreads();
    }
    d_T[blockIdx.x*512 + t] = acc;       // [(r*4+h)*16+p]*32 + m
}

// ---------------------------------------------------------------- pos scores (warp per (b,k))
__global__ void pos_kernel() {
    int g    = blockIdx.x*8 + (threadIdx.x >> 5);  // 0..8191
    int lane = threadIdx.x & 31;
    int b    = g >> 3;
    float score = 0.f;
    #pragma unroll
    for (int h = 0; h < H; ++h) {
        float pd = 0.f;
        if (lane < P) pd = d_polyQ[b*H*P + h*P + lane] * d_polyW[g*H*P + h*P + lane];
        #pragma unroll
        for (int o = 16; o; o >>= 1) pd += __shfl_xor_sync(0xffffffffu, pd, o);
        #pragma unroll
        for (int r = 0; r < R; ++r) {
            float fd = d_prfQ[b*R*H*M + r*H*M + h*M + lane] *
                       d_prfW[(size_t)g*R*H*M + r*H*M + h*M + lane];
            #pragma unroll
            for (int o = 16; o; o >>= 1) fd += __shfl_xor_sync(0xffffffffu, fd, o);
            score += pd * fd;
        }
    }
    if (lane == 0) d_pos[g] = score;
}

// ---------------------------------------------------------------- per-row loss terms
__global__ void rowloss_kernel(const float* __restrict__ label_mask) {
    __shared__ float red[256];
    int b = blockIdx.x, t = threadIdx.x;
    int r = t >> 7, h = (t >> 5) & 3, m = t & 31;
    const float* Tp = d_T + ((r*H + h)*P)*M + m;
    const float* pq = d_polyQ + b*H*P + h*P;
    float a = 0.f;
    #pragma unroll
    for (int p = 0; p < P; ++p) a += pq[p] * Tp[p*M];
    red[t] = d_prfQ[b*R*H*M + t] * a;
    __syncthreads();
    for (int s = 128; s > 0; s >>= 1) { if (t < s) red[t] += red[t+s]; __syncthreads(); }
    if (t == 0) {
        float S = red[0] + (float)NNEG * 1e-8f;   // neg row-sum + their +1e-8 terms
        float lg = 0.f;
        #pragma unroll
        for (int k = 0; k < KPOS; ++k) S += d_pos[b*KPOS + k] + 1e-8f;
        float logS = logf(S);
        #pragma unroll
        for (int k = 0; k < KPOS; ++k)
            lg += label_mask[b*KPOS + k] * (logf(d_pos[b*KPOS + k] + 1e-8f) - logS);
        d_numer[b] = lg;
    }
}

// ---------------------------------------------------------------- final reduction
__global__ void final_kernel(const float* __restrict__ label_mask, float* __restrict__ out) {
    __shared__ float r1[256], r2[256];
    int t = threadIdx.x;
    float a = 0.f, mm = 0.f;
    for (int i = t; i < B;       i += 256) a  += d_numer[i];
    for (int i = t; i < B*KPOS;  i += 256) mm += label_mask[i];
    r1[t] = a; r2[t] = mm;
    __syncthreads();
    for (int s = 128; s > 0; s >>= 1) {
        if (t < s) { r1[t] += r1[t+s]; r2[t] += r2[t+s]; }
        __syncthreads();
    }
    if (t == 0) out[0] = -r1[0] / (r2[0] + 1e-6f);
}

// ---------------------------------------------------------------- launch
extern "C" void kernel_launch(void* const* d_in, const int* in_sizes, int n_in,
                              void* d_out, int out_size) {
    const int*   indices    = (const int*)  d_in[0];
    const float* mask       = (const float*)d_in[1];
    const int*   labels     = (const int*)  d_in[2];
    const float* label_mask = (const float*)d_in[3];
    const int*   neg_idx    = (const int*)  d_in[4];
    const float* embed      = (const float*)d_in[5];
    const float* kernelM    = (const float*)d_in[6];
    const float* omega      = (const float*)d_in[7];
    const float* anchors    = (const float*)d_in[8];
    float* out = (float*)d_out;

    anch_kernel      <<<P,    HD >>>(anchors);
    query_feat_kernel<<<B,    256>>>(indices, mask, embed, omega);
    w_feat_kernel    <<<NW,   256>>>(labels, neg_idx, kernelM, omega);
    t_kernel         <<<R*H,  512>>>();
    pos_kernel       <<<B,    256>>>();
    rowloss_kernel   <<<B,    256>>>(label_mask);
    final_kernel     <<<1,    256>>>(label_mask, out);
}

// round 2
// speedup vs baseline: 2.3904x; 2.3904x over previous
#include <cuda_runtime.h>
#include <math.h>
#include <stdint.h>

// Problem constants (fixed shapes from setup_inputs)
#define B      1024
#define L      128
#define KPOS   8
#define NNEG   2048
#define NW     (B*KPOS + NNEG)   // 10240 W rows
#define EDIM   256
#define H      4
#define HD     64
#define P      16
#define M      32
#define R      2
#define NUML   131072

// Quadrature constants (double precision folded at compile time)
#define SQRT2_D 1.4142135623730951
#define CC      2.000001
__device__ __constant__ float c_s[2] = { (float)((2.0 - SQRT2_D)/CC), (float)((2.0 + SQRT2_D)/CC) };
__device__ __constant__ float c_w[2] = { (float)((2.0 + SQRT2_D)/(4.0*CC)), (float)((2.0 - SQRT2_D)/(4.0*CC)) };
#define INV_SQRT_M 0.17677669253f   // 1/sqrt(32.000001)

// Scratch (static device globals: allocation-free)
__device__ float d_anchT[HD*P];          // normalized anchors, transposed [d][p]
__device__ float d_omT  [HD*R*H*M];      // omega/8, transposed [d][r*128+h*32+m]
__device__ float d_polyQ[B*H*P];         // [b][h*16+p]
__device__ float d_prfQ [B*R*H*M];       // [b][r*128+h*32+m]
__device__ float d_polyW[NW*H*P];
__device__ float d_prfW [(size_t)NW*R*H*M];
__device__ float d_T    [R*H*P*M];       // [rh][p*32+m]
__device__ float d_numer[B];

__device__ __forceinline__ float warpsum(float v) {
    #pragma unroll
    for (int o = 16; o; o >>= 1) v += __shfl_xor_sync(0xffffffffu, v, o);
    return v;
}

// ---------------------------------------------------------------- prep: anchors + omega transpose + zero T
__global__ void prep_kernel(const float* __restrict__ anchors,
                            const float* __restrict__ omega) {
    int bx = blockIdx.x, t = threadIdx.x;   // 64 threads
    if (bx < P) {
        __shared__ float red[64];
        float v = anchors[bx*HD + t];
        red[t] = v*v;
        __syncthreads();
        for (int s = 32; s > 0; s >>= 1) { if (t < s) red[t] += red[t+s]; __syncthreads(); }
        d_anchT[t*P + bx] = v / sqrtf(red[0]);      // reference: no eps here
    } else if (bx < P + 256) {
        int e = (bx - P)*64 + t;                    // omega linear index [r][h][d][m]
        int m = e & 31, d = (e >> 5) & 63, h = (e >> 11) & 3, r = e >> 13;
        d_omT[d*256 + r*128 + h*32 + m] = omega[e] * 0.125f;   // fold /sqrt(HD)
    } else {
        d_T[(bx - (P + 256))*64 + t] = 0.f;
    }
}

// ---------------------------------------------------------------- shared feature math
// sq: per-head-normalized 256-vector in shared. Thread t -> (r,h,m) prf feature.
__device__ __forceinline__ void compute_feats(const float* sq,
                                              float* __restrict__ polyOut,
                                              float* __restrict__ prfOut,
                                              int t) {
    int r = t >> 7, h = (t >> 5) & 3;
    const float* x = sq + h*HD;
    float acc = 0.f;
    #pragma unroll
    for (int d = 0; d < HD; ++d)
        acc += x[d] * __ldg(&d_omT[d*256 + t]);    // coalesced: addr = d*256 + tid
    float s = c_s[r];
    float arg = acc * sqrtf(2.0f*s) - s;
    arg = fminf(fmaxf(arg, -20.f), 20.f);
    prfOut[t] = expf(arg) * (sqrtf(c_w[r]) * INV_SQRT_M);

    if (t < 64) {                                  // poly: (hh, p)
        int hh = t >> 4, p = t & 15;
        const float* xx = sq + hh*HD;
        float a = 0.f;
        #pragma unroll
        for (int d = 0; d < HD; ++d)
            a += xx[d] * d_anchT[d*P + p];         // coalesced over p
        a = fminf(fmaxf(a, -1.f), 1.f);
        polyOut[t] = a*a*0.25f;                    // ^2 / sqrt(P)
    }
}

// Normalize v (full 256 with eps, then per-head with eps) -> sq[t]. 3 BARs.
__device__ __forceinline__ void normalize_row(float v, float* sq,
                                              float* red, float* red2,
                                              int t, int lane, int warp) {
    float s1 = warpsum(v*v);
    if (lane == 0) red[warp] = s1;
    __syncthreads();
    float tot = red[0]+red[1]+red[2]+red[3]+red[4]+red[5]+red[6]+red[7];
    float qn = v / fmaxf(sqrtf(tot), 1e-4f);
    float s2 = warpsum(qn*qn);
    if (lane == 0) red2[warp] = s2;
    __syncthreads();
    int head = t >> 6;
    float hn = red2[head*2] + red2[head*2 + 1];
    sq[t] = qn / fmaxf(sqrtf(hn), 1e-4f);
    __syncthreads();
}

// ---------------------------------------------------------------- query features
__global__ void query_feat_kernel(const int* __restrict__ indices,
                                  const float* __restrict__ mask,
                                  const float* __restrict__ embed) {
    __shared__ __align__(16) float sq[256];
    __shared__ float red[8], red2[8], redm[8];
    __shared__ int   sidx[L];
    __shared__ float smk[L];
    int b = blockIdx.x, t = threadIdx.x, lane = t & 31, warp = t >> 5;

    if (t < L) { sidx[t] = indices[b*L + t]; smk[t] = mask[b*L + t]; }
    __syncthreads();

    float acc = 0.f;
    #pragma unroll 8
    for (int l = 0; l < L; ++l)
        acc += __ldg(embed + (size_t)sidx[l]*EDIM + t) * smk[l];

    float mv = (t < L) ? smk[t] : 0.f;
    mv = warpsum(mv);
    if (lane == 0) redm[warp] = mv;
    __syncthreads();
    float msum = redm[0]+redm[1]+redm[2]+redm[3];

    float q = acc / fmaxf(msum, 1.0f);
    normalize_row(q, sq, red, red2, t, lane, warp);
    compute_feats(sq, d_polyQ + b*H*P, d_prfQ + b*R*H*M, t);
}

// ---------------------------------------------------------------- W features
__global__ void w_feat_kernel(const int* __restrict__ labels,
                              const int* __restrict__ negidx,
                              const float* __restrict__ kernelM) {
    __shared__ __align__(16) float sq[256];
    __shared__ float red[8], red2[8];
    int i = blockIdx.x, t = threadIdx.x, lane = t & 31, warp = t >> 5;
    int j = (i < B*KPOS) ? max(labels[i], 0) : negidx[i - B*KPOS];
    float v = __ldg(kernelM + (size_t)t * NUML + j);
    normalize_row(v, sq, red, red2, t, lane, warp);
    compute_feats(sq, d_polyW + i*H*P, d_prfW + (size_t)i*R*H*M, t);
}

// ---------------------------------------------------------------- T = sum over neg rows of polyW (x) prfW
// grid = 64 chunks * 8 (r,h); each block handles 32 neg rows, atomicAdd into d_T.
__global__ void t_kernel() {
    int rh = blockIdx.x & 7;
    int chunk = blockIdx.x >> 3;
    int r = rh >> 2, h = rh & 3;
    int t = threadIdx.x;                 // 512 threads
    int p = t >> 5, m = t & 31;
    __shared__ float spw[32][16];
    __shared__ float spf[32][32];
    int base = B*KPOS + chunk*32;

    int lr = t >> 4, lp = t & 15;
    spw[lr][lp] = d_polyW[(base + lr)*H*P + h*P + lp];
    int fr = t >> 5, fm = t & 31;
    spf[fr     ][fm] = d_prfW[(size_t)(base+fr   )*R*H*M + r*H*M + h*M + fm];
    spf[fr + 16][fm] = d_prfW[(size_t)(base+fr+16)*R*H*M + r*H*M + h*M + fm];
    __syncthreads();

    float acc = 0.f;
    #pragma unroll
    for (int k = 0; k < 32; ++k) acc += spw[k][p]*spf[k][m];
    atomicAdd(&d_T[rh*512 + t], acc);
}

// ---------------------------------------------------------------- per-row loss (pos scores fused in)
__global__ void rowloss_kernel(const float* __restrict__ label_mask) {
    __shared__ float spos[8];
    __shared__ float red[8];
    int b = blockIdx.x, t = threadIdx.x, lane = t & 31, warp = t >> 5;

    // --- positive score: warp w computes k=w ---
    int g = b*KPOS + warp;
    float score = 0.f;
    #pragma unroll
    for (int h = 0; h < H; ++h) {
        float pd = (lane < P) ? d_polyQ[b*H*P + h*P + lane] * d_polyW[g*H*P + h*P + lane] : 0.f;
        pd = warpsum(pd);
        #pragma unroll
        for (int r = 0; r < R; ++r) {
            float fd = d_prfQ[b*R*H*M + r*H*M + h*M + lane] *
                       d_prfW[(size_t)g*R*H*M + r*H*M + h*M + lane];
            fd = warpsum(fd);
            score += pd * fd;
        }
    }
    if (lane == 0) spos[warp] = score;

    // --- negative row-sum via T: thread t -> (r,h,m) ---
    int r = t >> 7, h = (t >> 5) & 3, m = t & 31;
    const float* Tp = d_T + (r*4 + h)*512 + m;
    float a = 0.f;
    #pragma unroll
    for (int p = 0; p < P; ++p) a += d_polyQ[b*H*P + h*P + p] * Tp[p*32];
    float val = warpsum(d_prfQ[b*R*H*M + t] * a);
    if (lane == 0) red[warp] = val;
    __syncthreads();

    if (t == 0) {
        float S = (float)NNEG * 1e-8f;
        #pragma unroll
        for (int w = 0; w < 8; ++w) S += red[w];
        #pragma unroll
        for (int k = 0; k < KPOS; ++k) S += spos[k] + 1e-8f;
        float logS = logf(S);
        float lg = 0.f;
        #pragma unroll
        for (int k = 0; k < KPOS; ++k)
            lg += label_mask[b*KPOS + k] * (logf(spos[k] + 1e-8f) - logS);
        d_numer[b] = lg;
    }
}

// ---------------------------------------------------------------- final reduction
__global__ void final_kernel(const float* __restrict__ label_mask, float* __restrict__ out) {
    __shared__ float r1[256], r2[256];
    int t = threadIdx.x;
    float a = 0.f, mm = 0.f;
    for (int i = t; i < B;      i += 256) a  += d_numer[i];
    for (int i = t; i < B*KPOS; i += 256) mm += label_mask[i];
    r1[t] = a; r2[t] = mm;
    __syncthreads();
    for (int s = 128; s > 0; s >>= 1) {
        if (t < s) { r1[t] += r1[t+s]; r2[t] += r2[t+s]; }
        __syncthreads();
    }
    if (t == 0) out[0] = -r1[0] / (r2[0] + 1e-6f);
}

// ---------------------------------------------------------------- launch
extern "C" void kernel_launch(void* const* d_in, const int* in_sizes, int n_in,
                              void* d_out, int out_size) {
    const int*   indices    = (const int*)  d_in[0];
    const float* mask       = (const float*)d_in[1];
    const int*   labels     = (const int*)  d_in[2];
    const float* label_mask = (const float*)d_in[3];
    const int*   neg_idx    = (const int*)  d_in[4];
    const float* embed      = (const float*)d_in[5];
    const float* kernelM    = (const float*)d_in[6];
    const float* omega      = (const float*)d_in[7];
    const float* anchors    = (const float*)d_in[8];
    float* out = (float*)d_out;

    prep_kernel      <<<P + 256 + 64, 64 >>>(anchors, omega);
    query_feat_kernel<<<B,            256>>>(indices, mask, embed);
    w_feat_kernel    <<<NW,           256>>>(labels, neg_idx, kernelM);
    t_kernel         <<<8*64,         512>>>();
    rowloss_kernel   <<<B,            256>>>(label_mask);
    final_kernel     <<<1,            256>>>(label_mask, out);
}